// round 5
// baseline (speedup 1.0000x reference)
#include <cuda_runtime.h>
#include <math.h>

#define B_   128
#define P_   2048
#define NB_  2000
#define NF_  250
#define NC_  16
#define R_   128
#define LS_  1750      // NB - NF
#define FT_  1751      // NB - NF + 1
#define NW_  63        // 32-bit words covering NB=2000
#define NWP_ 64        // padded row stride in words

// ---------------- scratch (static device globals; no allocations) ----------------
__device__ float d_filt[FT_];
__device__ float d_stimdot[B_];
__device__ float d_gensig[B_ * LS_];
__device__ unsigned d_bm[B_ * NC_ * NWP_];   // bitmask of cc != 0

// ---------------- K1: filt_time[t] = sum_i stim_time[t+i] * stf[i] ----------------
__global__ void k_filt(const float* __restrict__ stim_time,
                       const float* __restrict__ stf) {
    int warp = (blockIdx.x * blockDim.x + threadIdx.x) >> 5;
    int lane = threadIdx.x & 31;
    if (warp >= FT_) return;
    double a = 0.0;
    #pragma unroll
    for (int i = lane; i < NF_; i += 32)
        a += (double)stim_time[warp + i] * (double)stf[i];
    #pragma unroll
    for (int m = 16; m; m >>= 1) a += __shfl_xor_sync(0xffffffffu, a, m);
    if (lane == 0) d_filt[warp] = (float)a;
}

// ---------------- K2: stim_dot[b] = sum_p spat[b,p] * sf[p] ----------------
__global__ void k_stimdot(const float* __restrict__ spat,
                          const float* __restrict__ sf) {
    int warp = (blockIdx.x * blockDim.x + threadIdx.x) >> 5;
    int lane = threadIdx.x & 31;
    if (warp >= B_) return;
    const float* row = spat + (size_t)warp * P_;
    double a = 0.0;
    for (int p = lane; p < P_; p += 32)
        a += (double)row[p] * (double)sf[p];
    #pragma unroll
    for (int m = 16; m; m >>= 1) a += __shfl_xor_sync(0xffffffffu, a, m);
    if (lane == 0) d_stimdot[warp] = (float)a;
}

// ---------------- K-pack: bitmask of cc != 0 ----------------
__global__ void k_pack(const float* __restrict__ cc) {
    int gid  = blockIdx.x * blockDim.x + threadIdx.x;
    int warp = gid >> 5;
    int lane = gid & 31;
    int row  = warp / NW_;
    int word = warp - row * NW_;
    if (row >= B_ * NC_) return;
    int elem = word * 32 + lane;
    float v = (elem < NB_) ? cc[(size_t)row * NB_ + elem] : 0.0f;
    unsigned m = __ballot_sync(0xffffffffu, v != 0.0f);
    if (lane == 0) d_bm[row * NWP_ + word] = m;
}

// ---------------- K3: gensig[b,t] ----------------
// 1 thread per t, 256 t per block; 4 rotating double accumulators break the
// serial DADD chain (depth 200 -> 50). Double reordering is bit-safe.
__global__ void __launch_bounds__(256)
k_gensig(const float* __restrict__ cK,
         const float* __restrict__ bias) {
    __shared__ double sKd[NC_ * 256];          // taps zero-padded 250 -> 256
    __shared__ unsigned sbm[NC_ * NWP_];

    const int tid = threadIdx.x;
    const int b   = blockIdx.y;

    for (int i = tid; i < NC_ * 256; i += 256) {
        int c = i >> 8, k = i & 255;
        sKd[i] = (k < NF_) ? (double)cK[c * NF_ + k] : 0.0;
    }
    for (int i = tid; i < NC_ * NWP_; i += 256)
        sbm[i] = d_bm[b * NC_ * NWP_ + i];
    __syncthreads();

    const int t = blockIdx.x * 256 + tid;
    if (t >= LS_) return;

    const int w0 = t >> 5;
    const int o  = t & 31;

    double a0 = 0.0, a1 = 0.0, a2 = 0.0, a3 = 0.0;
    #pragma unroll 1
    for (int c = 0; c < NC_; ++c) {
        const unsigned* bm = sbm + c * NWP_ + w0;
        const double*   kd = sKd + c * 256;
        #pragma unroll
        for (int k = 0; k < 8; k += 4) {
            unsigned w_0 = __funnelshift_r(bm[k],     bm[k + 1], o);
            unsigned w_1 = __funnelshift_r(bm[k + 1], bm[k + 2], o);
            unsigned w_2 = __funnelshift_r(bm[k + 2], bm[k + 3], o);
            unsigned w_3 = __funnelshift_r(bm[k + 3], bm[k + 4], o);
            while (w_0) { int i = __ffs(w_0) - 1; w_0 &= w_0 - 1; a0 += kd[((k    ) << 5) + i]; }
            while (w_1) { int i = __ffs(w_1) - 1; w_1 &= w_1 - 1; a1 += kd[((k + 1) << 5) + i]; }
            while (w_2) { int i = __ffs(w_2) - 1; w_2 &= w_2 - 1; a2 += kd[((k + 2) << 5) + i]; }
            while (w_3) { int i = __ffs(w_3) - 1; w_3 &= w_3 - 1; a3 += kd[((k + 3) << 5) + i]; }
        }
    }
    float coup = (float)((a0 + a1) + (a2 + a3));
    float sg = __fmul_rn(d_stimdot[b], d_filt[t]);
    sg = __fadd_rn(sg, bias[0]);
    d_gensig[b * LS_ + t] = __fadd_rn(sg, coup);
}

// ---------------- K4: sequential Bernoulli-GLM simulation ----------------
// 8 sequences per warp, 4 lanes each, 64 window positions per lane in
// registers, phase-rotated mod 64. OUTER BLOCK IS 64 STEPS so the mod-64
// phase re-aligns at each s reset (the R4 bug was 32-step blocks).
// Arithmetic bitwise identical to the verified chain: 4 serial 16-FMA
// chains A,B,C,D (= old lanes 4q..4q+3); (A+B)+(C+D) = old butterfly
// levels 1-2 (IEEE commutative); shfl_xor 1,2 = old levels 4,8.
__global__ void __launch_bounds__(128)
k_sim(const float* __restrict__ init,
      const float* __restrict__ ff,
      const float* __restrict__ u,
      float* __restrict__ out) {
    const unsigned FULL = 0xffffffffu;
    const int lane = threadIdx.x & 31;
    const int gw   = (blockIdx.x * blockDim.x + threadIdx.x) >> 5;  // 0..2047
    const int b    = gw >> 4;         // 16 warps per b
    const int rq   = gw & 15;         // 8-seq group within b
    const int half = lane >> 2;       // 0..7: sequence within the warp
    const int q    = lane & 3;        // lane within the 4-lane group
    const int seq  = b * R_ + rq * 8 + half;

    float f[64], w[64];
    #pragma unroll
    for (int i = 0; i < 64; ++i) {
        int k = q * 64 + i;
        bool valid = (k < NF_);
        f[i] = valid ? ff[k] : 0.0f;
        w[i] = valid ? init[b * NF_ + k] : 0.0f;
    }

    float* orow = out + (size_t)seq * NB_;
    for (int k = q; k < NF_; k += 4)
        orow[k] = init[b * NF_ + k];

    const float* gens = d_gensig + b * LS_;
    const int src_half  = lane & 28;                       // base lane of my 4-lane group
    const int src_shift = src_half | ((q + 1) & 3);        // next lane within group

    for (int t0 = 0; t0 < LS_; t0 += 64) {
        float gval0 = (t0 + lane      < LS_) ? gens[t0 + lane]      : 0.0f;
        float gval1 = (t0 + 32 + lane < LS_) ? gens[t0 + 32 + lane] : 0.0f;
        float uval[16], outv[16];
        #pragma unroll
        for (int m = 0; m < 16; ++m) {
            int t = t0 + 4 * m + q;
            uval[m] = (t < LS_) ? u[(size_t)t * (B_ * R_) + seq] : 0.0f;
            outv[m] = 0.0f;
        }

        #pragma unroll
        for (int s = 0; s < 64; ++s) {
            // four independent 16-deep chains (exact old per-lane partials)
            float A  = w[(s     ) & 63] * f[0];
            float Bc = w[(16 + s) & 63] * f[16];
            float C  = w[(32 + s) & 63] * f[32];
            float D  = w[(48 + s) & 63] * f[48];
            #pragma unroll
            for (int i = 1; i < 16; ++i) {
                A  = fmaf(w[(i      + s) & 63], f[i],      A);
                Bc = fmaf(w[(16 + i + s) & 63], f[16 + i], Bc);
                C  = fmaf(w[(32 + i + s) & 63], f[32 + i], C);
                D  = fmaf(w[(48 + i + s) & 63], f[48 + i], D);
            }
            float acc = (A + Bc) + (C + D);        // = old butterfly levels 1-2
            acc += __shfl_xor_sync(FULL, acc, 1);  // = old level 4
            acc += __shfl_xor_sync(FULL, acc, 2);  // = old level 8

            float gt = __shfl_sync(FULL, (s < 32) ? gval0 : gval1, s & 31);
            float ut = __shfl_sync(FULL, uval[s >> 2], src_half | (s & 3));

            float g = gt + acc;
            float e = expf(-g);
            float sig = 1.0f / (1.0f + e);
            float spike = (ut < sig) ? 1.0f : 0.0f;

            if (q == (s & 3)) outv[s >> 2] = spike;

            // shift: slot s&63 (tap 64q) <- neighbor's tap 64(q+1)
            float inc = __shfl_sync(FULL, w[s & 63], src_shift);
            w[s & 63] = inc;
            // insert new spike at position 249 (q==3, i==57) for phase s+1
            if (q == 3) w[(s + 58) & 63] = spike;
        }

        #pragma unroll
        for (int m = 0; m < 16; ++m) {
            int t = t0 + 4 * m + q;
            if (t < LS_) orow[NF_ + t] = outv[m];
        }
    }
}

// ---------------- launch ----------------
extern "C" void kernel_launch(void* const* d_in, const int* in_sizes, int n_in,
                              void* d_out, int out_size) {
    (void)in_sizes; (void)n_in; (void)out_size;
    const float* stim_spat = (const float*)d_in[0];
    const float* stim_time = (const float*)d_in[1];
    const float* init      = (const float*)d_in[2];
    const float* cc        = (const float*)d_in[3];
    const float* sf        = (const float*)d_in[4];
    const float* bias      = (const float*)d_in[5];
    const float* stf       = (const float*)d_in[6];
    const float* ff        = (const float*)d_in[7];
    const float* cK        = (const float*)d_in[8];
    const float* u         = (const float*)d_in[9];
    float* out = (float*)d_out;

    int pack_threads = B_ * NC_ * NW_ * 32;
    k_pack<<<(pack_threads + 255) / 256, 256>>>(cc);

    k_filt<<<(FT_ * 32 + 255) / 256, 256>>>(stim_time, stf);
    k_stimdot<<<(B_ * 32 + 255) / 256, 256>>>(stim_spat, sf);

    dim3 g3((LS_ + 255) / 256, B_);
    k_gensig<<<g3, 256>>>(cK, bias);

    // 2048 warps (8 sequences each) -> 512 blocks of 128 threads
    k_sim<<<512, 128>>>(init, ff, u, out);
}